// round 2
// baseline (speedup 1.0000x reference)
#include <cuda_runtime.h>

typedef unsigned long long u64;

#define HH    56
#define WW    56
#define CIN   64
#define COUT  64
#define TILE  8

// ---- packed f32x2 helpers (sm_103a) ----
__device__ __forceinline__ u64 addx2(u64 a, u64 b) {
    u64 r; asm("add.rn.f32x2 %0, %1, %2;" : "=l"(r) : "l"(a), "l"(b)); return r;
}
__device__ __forceinline__ u64 pack2(float lo, float hi) {
    u64 r; asm("mov.b64 %0, {%1, %2};" : "=l"(r) : "f"(lo), "f"(hi)); return r;
}
__device__ __forceinline__ void unpack2(u64 v, float& lo, float& hi) {
    asm("mov.b64 {%0, %1}, %2;" : "=f"(lo), "=f"(hi) : "l"(v));
}
// (a.hi, b.lo) — the "odd" straddling pair; ptxas folds the virtual movs.
__device__ __forceinline__ u64 mid2(u64 a, u64 b) {
    u64 r;
    asm("{\n\t.reg .b32 al, ah, bl, bh;\n\t"
        "mov.b64 {al, ah}, %1;\n\t"
        "mov.b64 {bl, bh}, %2;\n\t"
        "mov.b64 %0, {ah, bl};\n\t}"
        : "=l"(r) : "l"(a), "l"(b));
    return r;
}
__device__ __forceinline__ u64 abs2(u64 v) {  // clear both sign bits (2x LOP3, alu pipe)
    return v & 0x7FFFFFFF7FFFFFFFull;
}

// CTA: one n, one 8x8 output tile, all 64 output channels.
// 128 threads: py = tid&7 (tile row), cg = tid>>3 (0..15, 4 output channels each).
// Thread computes 8 pixels (its row) x 4 channels, pixels packed as 4 f32x2 pairs.
__global__ void __launch_bounds__(128)
adder2d_kernel(const float* __restrict__ x,
               const float* __restrict__ w,
               float* __restrict__ out)
{
    // x chunk: 8 input channels, 10x10 halo tile padded to 12-wide rows (f32x2 aligned)
    __shared__ __align__(16) float sx[8][120];
    // weight chunk: duplicated, pre-negated pairs (-w,-w): [ci_local][k][cout]
    __shared__ __align__(16) u64 swd[8][9][COUT];

    const int tid    = threadIdx.x;
    const int py     = tid & 7;
    const int cg     = tid >> 3;        // 0..15
    const int cobase = cg * 4;

    const int tx0 = blockIdx.x * TILE;
    const int ty0 = blockIdx.y * TILE;
    const int n   = blockIdx.z;

    const float* xn = x + (size_t)n * CIN * HH * WW;

    u64 acc[4][4];
    #pragma unroll
    for (int c = 0; c < 4; ++c)
        #pragma unroll
        for (int p = 0; p < 4; ++p) acc[c][p] = 0ull;

    for (int c8 = 0; c8 < 8; ++c8) {
        __syncthreads();   // previous chunk's compute done reading smem

        // ---- stage x chunk: 8 channels x 10 rows x 12 cols (cols 10,11 zero-pad) ----
        #pragma unroll
        for (int it = 0; it < 8; ++it) {            // 8*120 / 128 = 7.5 -> 8 iters
            int idx = it * 128 + tid;
            if (idx < 8 * 120) {
                int ci_l = idx / 120;
                int r    = idx - ci_l * 120;
                int row  = r / 12;
                int col  = r - row * 12;
                int gy   = ty0 + row - 1;
                int gx   = tx0 + col - 1;
                float v  = 0.0f;
                if (col < 10 && (unsigned)gy < (unsigned)HH && (unsigned)gx < (unsigned)WW)
                    v = xn[((c8 * 8 + ci_l) * HH + gy) * WW + gx];
                sx[ci_l][r] = v;
            }
        }

        // ---- stage weight chunk: 8 ci x 9 k x 64 co, negated + duplicated ----
        #pragma unroll
        for (int it = 0; it < 36; ++it) {           // 8*9*64 / 128 = 36 iters
            int idx  = it * 128 + tid;
            int co   = idx & 63;
            int rest = idx >> 6;                    // 0..71
            int k    = rest % 9;
            int ci_l = rest / 9;
            float wv = -w[(co * CIN + c8 * 8 + ci_l) * 9 + k];
            swd[ci_l][k][co] = pack2(wv, wv);
        }
        __syncthreads();

        // ---- compute ----
        #pragma unroll 2
        for (int ci_l = 0; ci_l < 8; ++ci_l) {
            #pragma unroll
            for (int kh = 0; kh < 3; ++kh) {
                const u64* rp = (const u64*)&sx[ci_l][(py + kh) * 12];
                u64 r0 = rp[0], r1 = rp[1], r2 = rp[2], r3 = rp[3], r4 = rp[4];
                u64 o0 = mid2(r0, r1), o1 = mid2(r1, r2),
                    o2 = mid2(r2, r3), o3 = mid2(r3, r4);

                #pragma unroll
                for (int kw = 0; kw < 3; ++kw) {
                    u64 p0 = (kw == 0) ? r0 : (kw == 1) ? o0 : r1;
                    u64 p1 = (kw == 0) ? r1 : (kw == 1) ? o1 : r2;
                    u64 p2 = (kw == 0) ? r2 : (kw == 1) ? o2 : r3;
                    u64 p3 = (kw == 0) ? r3 : (kw == 1) ? o3 : r4;
                    const int k = kh * 3 + kw;
                    #pragma unroll
                    for (int c = 0; c < 4; ++c) {
                        u64 w2 = swd[ci_l][k][cobase + c];   // broadcast LDS.64
                        acc[c][0] = addx2(acc[c][0], abs2(addx2(p0, w2)));
                        acc[c][1] = addx2(acc[c][1], abs2(addx2(p1, w2)));
                        acc[c][2] = addx2(acc[c][2], abs2(addx2(p2, w2)));
                        acc[c][3] = addx2(acc[c][3], abs2(addx2(p3, w2)));
                    }
                }
            }
        }
    }

    // ---- epilogue: out = -sum|x-w|; 2 float4 stores per channel ----
    #pragma unroll
    for (int c = 0; c < 4; ++c) {
        float f[8];
        #pragma unroll
        for (int p = 0; p < 4; ++p) {
            float lo, hi;
            unpack2(acc[c][p], lo, hi);
            f[2 * p]     = -lo;
            f[2 * p + 1] = -hi;
        }
        float* o = out + (((size_t)n * COUT + cobase + c) * HH + (ty0 + py)) * WW + tx0;
        ((float4*)o)[0] = make_float4(f[0], f[1], f[2], f[3]);
        ((float4*)o)[1] = make_float4(f[4], f[5], f[6], f[7]);
    }
}

extern "C" void kernel_launch(void* const* d_in, const int* in_sizes, int n_in,
                              void* d_out, int out_size)
{
    const float* x = (const float*)d_in[0];
    const float* w = (const float*)d_in[1];
    float* out     = (float*)d_out;

    dim3 grid(WW / TILE, HH / TILE, 16);   // 7 x 7 x 16 = 784 CTAs
    adder2d_kernel<<<grid, 128>>>(x, w, out);
}

// round 3
// speedup vs baseline: 1.1404x; 1.1404x over previous
#include <cuda_runtime.h>

typedef unsigned long long u64;

#define HH    56
#define WW    56
#define CIN   64
#define COUT  64
#define TILE  8

// ---- packed f32x2 helpers (sm_103a) ----
__device__ __forceinline__ u64 addx2(u64 a, u64 b) {
    u64 r; asm("add.rn.f32x2 %0, %1, %2;" : "=l"(r) : "l"(a), "l"(b)); return r;
}
__device__ __forceinline__ u64 pack2(float lo, float hi) {
    u64 r; asm("mov.b64 %0, {%1, %2};" : "=l"(r) : "f"(lo), "f"(hi)); return r;
}
__device__ __forceinline__ void unpack2(u64 v, float& lo, float& hi) {
    asm("mov.b64 {%0, %1}, %2;" : "=f"(lo), "=f"(hi) : "l"(v));
}
// (a.hi, b.lo) — straddling pair; virtual movs fold in SASS.
__device__ __forceinline__ u64 mid2(u64 a, u64 b) {
    u64 r;
    asm("{\n\t.reg .b32 al, ah, bl, bh;\n\t"
        "mov.b64 {al, ah}, %1;\n\t"
        "mov.b64 {bl, bh}, %2;\n\t"
        "mov.b64 %0, {ah, bl};\n\t}"
        : "=l"(r) : "l"(a), "l"(b));
    return r;
}
__device__ __forceinline__ u64 abs2(u64 v) {  // 2x LOP3 on alu pipe
    return v & 0x7FFFFFFF7FFFFFFFull;
}

// CTA: one n, one 8x8 tile, HALF the output channels (32).
// 128 threads: py = tid&7 (tile row), cg = tid>>3 (0..15 -> 2 channels each).
// Thread: 8 pixels (4 f32x2 pairs) x 2 channels -> 8 u64 accumulators.
__global__ void __launch_bounds__(128, 6)
adder2d_kernel(const float* __restrict__ x,
               const float* __restrict__ w,
               float* __restrict__ out)
{
    __shared__ __align__(16) float sx[8][120];       // 8 ci x 10 rows x 12 cols (pad)
    __shared__ __align__(16) u64   swd[8][9][32];    // dup (-w,-w) pairs, 18.4 KB

    const int tid  = threadIdx.x;
    const int py   = tid & 7;
    const int cg   = tid >> 3;            // 0..15
    const int co2  = cg * 2;              // local channel base (even -> 16B aligned)

    const int tx0    = blockIdx.x * TILE;
    const int ty0    = blockIdx.y * TILE;
    const int n      = blockIdx.z >> 1;
    const int cohalf = blockIdx.z & 1;
    const int cobase = cohalf * 32;

    const float* xn = x + (size_t)n * CIN * HH * WW;

    u64 acc[2][4];
    #pragma unroll
    for (int c = 0; c < 2; ++c)
        #pragma unroll
        for (int p = 0; p < 4; ++p) acc[c][p] = 0ull;

    for (int c8 = 0; c8 < 8; ++c8) {
        __syncthreads();

        // ---- stage x chunk: 8 ci x 10 x 12 (cols 10,11 + borders zero) ----
        #pragma unroll
        for (int it = 0; it < 8; ++it) {
            int idx = it * 128 + tid;
            if (idx < 8 * 120) {
                int ci_l = idx / 120;
                int r    = idx - ci_l * 120;
                int row  = r / 12;
                int col  = r - row * 12;
                int gy   = ty0 + row - 1;
                int gx   = tx0 + col - 1;
                float v  = 0.0f;
                if (col < 10 && (unsigned)gy < (unsigned)HH && (unsigned)gx < (unsigned)WW)
                    v = xn[((c8 * 8 + ci_l) * HH + gy) * WW + gx];
                sx[ci_l][r] = v;
            }
        }

        // ---- stage weights: 8 ci x 9 k x 32 co, negated + duplicated ----
        #pragma unroll
        for (int it = 0; it < 18; ++it) {             // 2304 / 128
            int idx  = it * 128 + tid;
            int co   = idx & 31;
            int rest = idx >> 5;                      // 0..71
            int k    = rest % 9;
            int ci_l = rest / 9;
            float wv = -w[((cobase + co) * CIN + c8 * 8 + ci_l) * 9 + k];
            swd[ci_l][k][co] = pack2(wv, wv);
        }
        __syncthreads();

        // ---- compute ----
        #pragma unroll 2
        for (int ci_l = 0; ci_l < 8; ++ci_l) {
            #pragma unroll
            for (int kh = 0; kh < 3; ++kh) {
                const u64* rp = (const u64*)&sx[ci_l][(py + kh) * 12];
                u64 r0 = rp[0], r1 = rp[1], r2 = rp[2], r3 = rp[3], r4 = rp[4];
                u64 o0 = mid2(r0, r1), o1 = mid2(r1, r2),
                    o2 = mid2(r2, r3), o3 = mid2(r3, r4);

                #pragma unroll
                for (int kw = 0; kw < 3; ++kw) {
                    u64 p0 = (kw == 0) ? r0 : (kw == 1) ? o0 : r1;
                    u64 p1 = (kw == 0) ? r1 : (kw == 1) ? o1 : r2;
                    u64 p2 = (kw == 0) ? r2 : (kw == 1) ? o2 : r3;
                    u64 p3 = (kw == 0) ? r3 : (kw == 1) ? o3 : r4;
                    const int k = kh * 3 + kw;
                    // one LDS.128 fetches both channels' (-w,-w) pairs
                    ulonglong2 wp = *(const ulonglong2*)&swd[ci_l][k][co2];
                    acc[0][0] = addx2(acc[0][0], abs2(addx2(p0, wp.x)));
                    acc[0][1] = addx2(acc[0][1], abs2(addx2(p1, wp.x)));
                    acc[0][2] = addx2(acc[0][2], abs2(addx2(p2, wp.x)));
                    acc[0][3] = addx2(acc[0][3], abs2(addx2(p3, wp.x)));
                    acc[1][0] = addx2(acc[1][0], abs2(addx2(p0, wp.y)));
                    acc[1][1] = addx2(acc[1][1], abs2(addx2(p1, wp.y)));
                    acc[1][2] = addx2(acc[1][2], abs2(addx2(p2, wp.y)));
                    acc[1][3] = addx2(acc[1][3], abs2(addx2(p3, wp.y)));
                }
            }
        }
    }

    // ---- epilogue: out = -sum|x-w| ----
    #pragma unroll
    for (int c = 0; c < 2; ++c) {
        float f[8];
        #pragma unroll
        for (int p = 0; p < 4; ++p) {
            float lo, hi;
            unpack2(acc[c][p], lo, hi);
            f[2 * p]     = -lo;
            f[2 * p + 1] = -hi;
        }
        float* o = out + (((size_t)n * COUT + cobase + co2 + c) * HH + (ty0 + py)) * WW + tx0;
        ((float4*)o)[0] = make_float4(f[0], f[1], f[2], f[3]);
        ((float4*)o)[1] = make_float4(f[4], f[5], f[6], f[7]);
    }
}

extern "C" void kernel_launch(void* const* d_in, const int* in_sizes, int n_in,
                              void* d_out, int out_size)
{
    const float* x = (const float*)d_in[0];
    const float* w = (const float*)d_in[1];
    float* out     = (float*)d_out;

    dim3 grid(WW / TILE, HH / TILE, 32);   // 7 x 7 x (16 n * 2 co-halves) = 1568 CTAs
    adder2d_kernel<<<grid, 128>>>(x, w, out);
}

// round 4
// speedup vs baseline: 1.1615x; 1.0185x over previous
#include <cuda_runtime.h>

typedef unsigned long long u64;

#define HH    56
#define WW    56
#define CIN   64
#define COUT  64
#define TILE  8

// ---- packed f32x2 helpers (sm_103a) ----
__device__ __forceinline__ u64 addx2(u64 a, u64 b) {
    u64 r; asm("add.rn.f32x2 %0, %1, %2;" : "=l"(r) : "l"(a), "l"(b)); return r;
}
__device__ __forceinline__ u64 pack2(float lo, float hi) {
    u64 r; asm("mov.b64 %0, {%1, %2};" : "=l"(r) : "f"(lo), "f"(hi)); return r;
}
__device__ __forceinline__ void unpack2(u64 v, float& lo, float& hi) {
    asm("mov.b64 {%0, %1}, %2;" : "=f"(lo), "=f"(hi) : "l"(v));
}
// (a.hi, b.lo) — straddling pair
__device__ __forceinline__ u64 mid2(u64 a, u64 b) {
    u64 r;
    asm("{\n\t.reg .b32 al, ah, bl, bh;\n\t"
        "mov.b64 {al, ah}, %1;\n\t"
        "mov.b64 {bl, bh}, %2;\n\t"
        "mov.b64 %0, {ah, bl};\n\t}"
        : "=l"(r) : "l"(a), "l"(b));
    return r;
}
__device__ __forceinline__ u64 abs2(u64 v) {  // 2x LOP3 on alu pipe
    return v & 0x7FFFFFFF7FFFFFFFull;
}

__shared__ __align__(16) float sx_buf[2][8][120];     // x chunks, 2 x 3.84 KB
__shared__ __align__(16) u64   swd_buf[2][8][9][32];  // dup (-w,-w), 2 x 18.4 KB

__device__ __forceinline__ void stage_chunk(
    int buf, int c8, int tid, int tx0, int ty0, int cobase,
    const float* __restrict__ xn, const float* __restrict__ w)
{
    // ---- x chunk: 8 ci x 10 rows x 12 cols (cols 10,11 + borders zero) ----
    #pragma unroll
    for (int it = 0; it < 8; ++it) {
        int idx = it * 128 + tid;
        if (idx < 8 * 120) {
            int ci_l = idx / 120;
            int r    = idx - ci_l * 120;
            int row  = r / 12;
            int col  = r - row * 12;
            int gy   = ty0 + row - 1;
            int gx   = tx0 + col - 1;
            float v  = 0.0f;
            if (col < 10 && (unsigned)gy < (unsigned)HH && (unsigned)gx < (unsigned)WW)
                v = xn[((c8 * 8 + ci_l) * HH + gy) * WW + gx];
            sx_buf[buf][ci_l][r] = v;
        }
    }
    // ---- weights: 8 ci x 9 k x 32 co, negated + duplicated ----
    #pragma unroll
    for (int it = 0; it < 18; ++it) {                 // 2304 / 128
        int idx  = it * 128 + tid;
        int co   = idx & 31;
        int rest = idx >> 5;                          // 0..71
        int k    = rest % 9;
        int ci_l = rest / 9;
        float wv = -w[((cobase + co) * CIN + c8 * 8 + ci_l) * 9 + k];
        swd_buf[buf][ci_l][k][co] = pack2(wv, wv);
    }
}

// CTA: one n, one 8x8 tile, 32 output channels.
// 128 threads: py = tid&7, cg = tid>>3 (2 channels each).
// Thread: 8 pixels (4 f32x2 pairs) x 2 channels -> 8 u64 accumulators.
__global__ void __launch_bounds__(128, 5)
adder2d_kernel(const float* __restrict__ x,
               const float* __restrict__ w,
               float* __restrict__ out)
{
    const int tid  = threadIdx.x;
    const int py   = tid & 7;
    const int cg   = tid >> 3;
    const int co2  = cg * 2;

    const int tx0    = blockIdx.x * TILE;
    const int ty0    = blockIdx.y * TILE;
    const int n      = blockIdx.z >> 1;
    const int cobase = (blockIdx.z & 1) * 32;

    const float* xn = x + (size_t)n * CIN * HH * WW;

    u64 acc[2][4];
    #pragma unroll
    for (int c = 0; c < 2; ++c)
        #pragma unroll
        for (int p = 0; p < 4; ++p) acc[c][p] = 0ull;

    // prologue: stage chunk 0 into buffer 0
    stage_chunk(0, 0, tid, tx0, ty0, cobase, xn, w);

    for (int c8 = 0; c8 < 8; ++c8) {
        const int cb = c8 & 1;
        // Guarantees: buf[cb] fully staged (all threads), and buf[cb^1]'s
        // previous compute readers are done -> safe to overwrite below.
        __syncthreads();

        if (c8 < 7)
            stage_chunk(cb ^ 1, c8 + 1, tid, tx0, ty0, cobase, xn, w);

        // ---- compute on buf[cb]; LDGs for next chunk are in flight above ----
        #pragma unroll 2
        for (int ci_l = 0; ci_l < 8; ++ci_l) {
            #pragma unroll
            for (int kh = 0; kh < 3; ++kh) {
                const u64* rp = (const u64*)&sx_buf[cb][ci_l][(py + kh) * 12];
                u64 r0 = rp[0], r1 = rp[1], r2 = rp[2], r3 = rp[3], r4 = rp[4];
                u64 o0 = mid2(r0, r1), o1 = mid2(r1, r2),
                    o2 = mid2(r2, r3), o3 = mid2(r3, r4);

                #pragma unroll
                for (int kw = 0; kw < 3; ++kw) {
                    u64 p0 = (kw == 0) ? r0 : (kw == 1) ? o0 : r1;
                    u64 p1 = (kw == 0) ? r1 : (kw == 1) ? o1 : r2;
                    u64 p2 = (kw == 0) ? r2 : (kw == 1) ? o2 : r3;
                    u64 p3 = (kw == 0) ? r3 : (kw == 1) ? o3 : r4;
                    const int k = kh * 3 + kw;
                    ulonglong2 wp = *(const ulonglong2*)&swd_buf[cb][ci_l][k][co2];
                    acc[0][0] = addx2(acc[0][0], abs2(addx2(p0, wp.x)));
                    acc[0][1] = addx2(acc[0][1], abs2(addx2(p1, wp.x)));
                    acc[0][2] = addx2(acc[0][2], abs2(addx2(p2, wp.x)));
                    acc[0][3] = addx2(acc[0][3], abs2(addx2(p3, wp.x)));
                    acc[1][0] = addx2(acc[1][0], abs2(addx2(p0, wp.y)));
                    acc[1][1] = addx2(acc[1][1], abs2(addx2(p1, wp.y)));
                    acc[1][2] = addx2(acc[1][2], abs2(addx2(p2, wp.y)));
                    acc[1][3] = addx2(acc[1][3], abs2(addx2(p3, wp.y)));
                }
            }
        }
    }

    // ---- epilogue: out = -sum|x-w| ----
    #pragma unroll
    for (int c = 0; c < 2; ++c) {
        float f[8];
        #pragma unroll
        for (int p = 0; p < 4; ++p) {
            float lo, hi;
            unpack2(acc[c][p], lo, hi);
            f[2 * p]     = -lo;
            f[2 * p + 1] = -hi;
        }
        float* o = out + (((size_t)n * COUT + cobase + co2 + c) * HH + (ty0 + py)) * WW + tx0;
        ((float4*)o)[0] = make_float4(f[0], f[1], f[2], f[3]);
        ((float4*)o)[1] = make_float4(f[4], f[5], f[6], f[7]);
    }
}

extern "C" void kernel_launch(void* const* d_in, const int* in_sizes, int n_in,
                              void* d_out, int out_size)
{
    const float* x = (const float*)d_in[0];
    const float* w = (const float*)d_in[1];
    float* out     = (float*)d_out;

    dim3 grid(WW / TILE, HH / TILE, 32);   // 7 x 7 x (16 n * 2 co-halves) = 1568 CTAs
    adder2d_kernel<<<grid, 128>>>(x, w, out);
}